// round 11
// baseline (speedup 1.0000x reference)
#include <cuda_runtime.h>
#include <cstdint>

// MeanAggregator: multi-pass L2 temporal blocking + smem-queue compacted gathers.
// out[b,:] = mean_k table[neighs[b,k],:], B=50000, K=32, table 500000x128 f32.
//
// 4 launches; pass p keeps segment [p*125K,(p+1)*125K) (64MB) L2-resident
// (+ out 26MB RMW + idx 13MB < 126MB L2). Each warp owns 8 nodes.
// Phase A: ballot + prefix-popc scatter of in-segment indices into a per-warp
//          smem queue (no loops in the load path).
// Phase B: consume queue with an unrolled-by-4 PREDICATED loop: LDS of queue
//          entries has no dependence on outstanding gathers; unrolled slots get
//          distinct registers -> sustained MLP~4 (fixes the WAR-serialized
//          while-loops that pinned R7/R8/R9 at ~3TB/s). Padding slots clamp to
//          the segment base row (hot, L1-hit) and are masked via FMA.

#define BATCH   50000
#define DEGREE  32
#define D_FEAT  128
#define WARPS_PER_BLOCK 8
#define THREADS 256
#define NODES   8
#define NSEG    4
#define SEG     (500000 / NSEG)
#define FULL    0xffffffffu

__device__ int g_idx_is64;

// int64 indices in [0,500000) have all odd 32-bit words == 0; int32 data has
// random values there (P(128 zeros) ~ 0).
__global__ void detect_idx_dtype(const unsigned int* __restrict__ n32)
{
    bool all_zero = true;
    #pragma unroll
    for (int i = 1; i < 256; i += 2) {
        if (n32[i] != 0u) { all_zero = false; break; }
    }
    g_idx_is64 = all_zero ? 1 : 0;
}

__global__ __launch_bounds__(THREADS)
void mean_agg_pass(const void* __restrict__ neighs_raw,
                   const float4* __restrict__ table,  // [500000, 32] float4
                   float4* __restrict__ out,          // [50000, 32] float4
                   int pass)
{
    // Per-warp index queue: 8 nodes x up to 32 in-segment indices. 8KB/block.
    __shared__ int queue[WARPS_PER_BLOCK][NODES][DEGREE];

    const int w     = threadIdx.x >> 5;
    const int lane  = threadIdx.x & 31;
    const int gwarp = (blockIdx.x * THREADS + threadIdx.x) >> 5;
    const int base  = gwarp * NODES;
    if (base >= BATCH) return;

    const int lo = pass * SEG;

    // ---- Phase A: ballot + scatter in-segment indices to smem queue ----
    int cnt[NODES];
    #pragma unroll
    for (int n = 0; n < NODES; ++n) {
        const int node = base + n;
        int my = 0;
        bool in = false;
        if (node < BATCH) {
            if (g_idx_is64) {
                my = (int)__ldg(&((const long long*)neighs_raw)
                                [(size_t)node * DEGREE + lane]);
            } else {
                my = __ldg(&((const int*)neighs_raw)
                           [(size_t)node * DEGREE + lane]);
            }
            in = (unsigned)(my - lo) < (unsigned)SEG;
        }
        const unsigned m = __ballot_sync(FULL, in);
        if (in) {
            const int rank = __popc(m & ((1u << lane) - 1u));
            queue[w][n][rank] = my;
        }
        cnt[n] = __popc(m);
    }
    __syncwarp();

    // ---- Phase B: unrolled predicated consumption (MLP ~4) ----
    float4 acc[NODES];
    #pragma unroll
    for (int n = 0; n < NODES; ++n)
        acc[n] = make_float4(0.f, 0.f, 0.f, 0.f);

    #pragma unroll
    for (int n = 0; n < NODES; ++n) {
        const int c = cnt[n];
        for (int j = 0; j < c; j += 4) {
            float4 v[4];
            float  mk[4];
            #pragma unroll
            for (int t = 0; t < 4; ++t) {
                const bool val = (j + t) < c;
                // Reading a garbage slot is safe (smem); the index is replaced
                // by the hot segment-base row before it forms an address.
                const int q    = queue[w][n][(j + t) & (DEGREE - 1)];
                const int safe = val ? q : lo;
                mk[t] = val ? 1.0f : 0.0f;
                v[t]  = __ldg(&table[(size_t)safe * (D_FEAT / 4) + lane]);
            }
            #pragma unroll
            for (int t = 0; t < 4; ++t) {
                acc[n].x = fmaf(v[t].x, mk[t], acc[n].x);
                acc[n].y = fmaf(v[t].y, mk[t], acc[n].y);
                acc[n].z = fmaf(v[t].z, mk[t], acc[n].z);
                acc[n].w = fmaf(v[t].w, mk[t], acc[n].w);
            }
        }
    }

    // ---- Out RMW: partial sums stay L2-resident across passes ----
    #pragma unroll
    for (int n = 0; n < NODES; ++n) {
        const int node = base + n;
        if (node >= BATCH) break;
        float4* o = &out[(size_t)node * (D_FEAT / 4) + lane];
        float4 a = acc[n];
        if (pass != 0) {
            const float4 p = *o;
            a.x += p.x; a.y += p.y; a.z += p.z; a.w += p.w;
        }
        if (pass == NSEG - 1) {
            const float s = 1.0f / (float)DEGREE;
            a.x *= s; a.y *= s; a.z *= s; a.w *= s;
        }
        *o = a;
    }
}

extern "C" void kernel_launch(void* const* d_in, const int* in_sizes, int n_in,
                              void* d_out, int out_size)
{
    const void*   neighs = d_in[0];
    const float4* table  = (const float4*)d_in[1];
    float4*       out    = (float4*)d_out;

    detect_idx_dtype<<<1, 1>>>((const unsigned int*)neighs);

    const int warps_needed = (BATCH + NODES - 1) / NODES;                  // 6250
    const int blocks = (warps_needed + WARPS_PER_BLOCK - 1) / WARPS_PER_BLOCK;  // 782
    for (int p = 0; p < NSEG; ++p)
        mean_agg_pass<<<blocks, THREADS>>>(neighs, table, out, p);
}

// round 12
// speedup vs baseline: 1.9912x; 1.9912x over previous
#include <cuda_runtime.h>
#include <cstdint>

// MeanAggregator: single-pass dense gather (proven 6.4TB/s engine) + inlined
// dtype detection + persistent grid-stride (no wave tail, no serial pre-kernel).
// out[b,:] = mean_k table[neighs[b,k],:], B=50000, K=32, table 500000x128 f32.
//
// One warp per node per iteration. Lane = (half, sub): half = neighbor parity,
// sub = 32B slice of the 512B row. 16 fixed iterations of paired 256-bit
// evict_last gathers; fold halves with one shfl_xor(16); lanes 0-15 store.

#define BATCH   50000
#define DEGREE  32
#define D_FEAT  128
#define THREADS 256
#define BLOCKS  888          // 148 SMs x 6 resident blocks (regs~40)
#define FULL    0xffffffffu

struct F8 { float v[8]; };

__device__ __forceinline__ F8 ldg_evict_last_v8(const float* p)
{
    F8 r;
    asm volatile(
        "ld.global.nc.L2::evict_last.v8.b32 {%0,%1,%2,%3,%4,%5,%6,%7}, [%8];"
        : "=f"(r.v[0]), "=f"(r.v[1]), "=f"(r.v[2]), "=f"(r.v[3]),
          "=f"(r.v[4]), "=f"(r.v[5]), "=f"(r.v[6]), "=f"(r.v[7])
        : "l"(p));
    return r;
}

__device__ __forceinline__ void stg_streaming_v4(float4* p, float4 v)
{
    asm volatile("st.global.cs.v4.f32 [%0], {%1,%2,%3,%4};"
                 :: "l"(p), "f"(v.x), "f"(v.y), "f"(v.z), "f"(v.w)
                 : "memory");
}

__global__ __launch_bounds__(THREADS)
void mean_agg_kernel(const void* __restrict__ neighs_raw,
                     const float* __restrict__ table,   // [500000, 128] f32
                     float4* __restrict__ out)          // [50000, 32] float4
{
    const int lane = threadIdx.x & 31;
    const int half = lane >> 4;   // neighbor parity this lane serves
    const int sub  = lane & 15;   // 32B slice of the 512B row

    // Inline dtype detection: int64 indices in [0,500000) have zero odd words;
    // int32 data has random indices there (P(4 zeros) ~ 1.6e-23). Broadcast
    // loads, hot in L1/L2 -> negligible.
    const unsigned* n32 = (const unsigned*)neighs_raw;
    const bool is64 = ((n32[1] | n32[3] | n32[5] | n32[7]) == 0u);

    const int warp0      = (blockIdx.x * THREADS + threadIdx.x) >> 5;
    const int warp_count = BLOCKS * (THREADS / 32);

    for (int node = warp0; node < BATCH; node += warp_count) {
        // Coalesced streaming load of this node's 32 indices (lane k -> idx k).
        int my_idx;
        if (is64) {
            my_idx = (int)__ldcs(&((const long long*)neighs_raw)
                                 [(size_t)node * DEGREE + lane]);
        } else {
            my_idx = __ldcs(&((const int*)neighs_raw)
                            [(size_t)node * DEGREE + lane]);
        }

        float acc[8] = {0.f, 0.f, 0.f, 0.f, 0.f, 0.f, 0.f, 0.f};

        #pragma unroll 4
        for (int k = 0; k < DEGREE / 2; ++k) {
            const int idx = __shfl_sync(FULL, my_idx, 2 * k + half);
            const F8 r = ldg_evict_last_v8(&table[(size_t)idx * D_FEAT + sub * 8]);
            #pragma unroll
            for (int i = 0; i < 8; ++i) acc[i] += r.v[i];
        }

        // Fold halves: lanes l and l^16 hold the same columns, disjoint k-sets.
        #pragma unroll
        for (int i = 0; i < 8; ++i)
            acc[i] += __shfl_xor_sync(FULL, acc[i], 16);

        if (half == 0) {
            const float s = 1.0f / (float)DEGREE;
            float4 lo = make_float4(acc[0] * s, acc[1] * s, acc[2] * s, acc[3] * s);
            float4 hi = make_float4(acc[4] * s, acc[5] * s, acc[6] * s, acc[7] * s);
            float4* dst = &out[(size_t)node * (D_FEAT / 4) + sub * 2];
            stg_streaming_v4(dst, lo);
            stg_streaming_v4(dst + 1, hi);
        }
    }
}

extern "C" void kernel_launch(void* const* d_in, const int* in_sizes, int n_in,
                              void* d_out, int out_size)
{
    const void*  neighs = d_in[0];
    const float* table  = (const float*)d_in[1];
    float4*      out    = (float4*)d_out;

    mean_agg_kernel<<<BLOCKS, THREADS>>>(neighs, table, out);
}

// round 13
// speedup vs baseline: 2.1832x; 1.0964x over previous
#include <cuda_runtime.h>
#include <cstdint>

// MeanAggregator: single-pass dense gather — R4 champion engine with inlined
// dtype detection (no serialized pre-kernel).
// out[b,:] = mean_k table[neighs[b,k],:], B=50000, K=32, table 500000x128 f32.
//
// One warp per node (short-lived CTAs: scheduler overlaps warp drain with
// fresh CTAs' index loads — measured 13% faster than persistent grid-stride).
// Lane = (half, sub): half = neighbor parity, sub = 32B slice of the 512B row.
// 16 fixed iterations of paired 256-bit evict_last gathers; fold halves with
// one shfl_xor(16); lanes 0-15 store the row with streaming stores.

#define BATCH   50000
#define DEGREE  32
#define D_FEAT  128
#define WARPS_PER_BLOCK 8
#define THREADS (WARPS_PER_BLOCK * 32)
#define FULL    0xffffffffu

struct F8 { float v[8]; };

__device__ __forceinline__ F8 ldg_evict_last_v8(const float* p)
{
    F8 r;
    asm volatile(
        "ld.global.nc.L2::evict_last.v8.b32 {%0,%1,%2,%3,%4,%5,%6,%7}, [%8];"
        : "=f"(r.v[0]), "=f"(r.v[1]), "=f"(r.v[2]), "=f"(r.v[3]),
          "=f"(r.v[4]), "=f"(r.v[5]), "=f"(r.v[6]), "=f"(r.v[7])
        : "l"(p));
    return r;
}

__device__ __forceinline__ void stg_streaming_v4(float4* p, float4 v)
{
    asm volatile("st.global.cs.v4.f32 [%0], {%1,%2,%3,%4};"
                 :: "l"(p), "f"(v.x), "f"(v.y), "f"(v.z), "f"(v.w)
                 : "memory");
}

__global__ __launch_bounds__(THREADS)
void mean_agg_kernel(const void* __restrict__ neighs_raw,
                     const float* __restrict__ table,   // [500000, 128] f32
                     float4* __restrict__ out)          // [50000, 32] float4
{
    const int warp = (blockIdx.x * THREADS + threadIdx.x) >> 5;
    const int lane = threadIdx.x & 31;
    if (warp >= BATCH) return;

    const int half = lane >> 4;   // neighbor parity this lane serves
    const int sub  = lane & 15;   // 32B slice of the 512B row

    // Inline dtype detection: int64 indices in [0,500000) have zero odd 32-bit
    // words; int32 data has random indices there (P(4 zeros) ~ 1.6e-23).
    // Same cache line for all warps -> broadcast L1/L2 hit, off critical path.
    const unsigned* n32 = (const unsigned*)neighs_raw;
    const bool is64 = ((n32[1] | n32[3] | n32[5] | n32[7]) == 0u);

    // One coalesced streaming load of this node's 32 indices (lane k -> idx k).
    int my_idx;
    if (is64) {
        my_idx = (int)__ldcs(&((const long long*)neighs_raw)
                             [(size_t)warp * DEGREE + lane]);
    } else {
        my_idx = __ldcs(&((const int*)neighs_raw)
                        [(size_t)warp * DEGREE + lane]);
    }

    float acc[8] = {0.f, 0.f, 0.f, 0.f, 0.f, 0.f, 0.f, 0.f};

    #pragma unroll 4
    for (int k = 0; k < DEGREE / 2; ++k) {
        const int idx = __shfl_sync(FULL, my_idx, 2 * k + half);
        const F8 r = ldg_evict_last_v8(&table[(size_t)idx * D_FEAT + sub * 8]);
        #pragma unroll
        for (int i = 0; i < 8; ++i) acc[i] += r.v[i];
    }

    // Fold halves: lanes l and l^16 hold the same columns, disjoint k-sets.
    #pragma unroll
    for (int i = 0; i < 8; ++i)
        acc[i] += __shfl_xor_sync(FULL, acc[i], 16);

    if (half == 0) {
        const float s = 1.0f / (float)DEGREE;
        float4 lo = make_float4(acc[0] * s, acc[1] * s, acc[2] * s, acc[3] * s);
        float4 hi = make_float4(acc[4] * s, acc[5] * s, acc[6] * s, acc[7] * s);
        float4* dst = &out[(size_t)warp * (D_FEAT / 4) + sub * 2];
        stg_streaming_v4(dst, lo);
        stg_streaming_v4(dst + 1, hi);
    }
}

extern "C" void kernel_launch(void* const* d_in, const int* in_sizes, int n_in,
                              void* d_out, int out_size)
{
    const void*  neighs = d_in[0];
    const float* table  = (const float*)d_in[1];
    float4*      out    = (float4*)d_out;

    const int blocks = (BATCH + WARPS_PER_BLOCK - 1) / WARPS_PER_BLOCK;
    mean_agg_kernel<<<blocks, THREADS>>>(neighs, table, out);
}

// round 14
// speedup vs baseline: 2.1991x; 1.0073x over previous
#include <cuda_runtime.h>
#include <cstdint>

// MeanAggregator: single-pass dense gather, champion engine.
// out[b,:] = mean_k table[neighs[b,k],:], B=50000, K=32, table 500000x128 f32.
//
// One warp per node, short-lived CTAs (scheduler overlaps warp drain with new
// CTAs' index loads). Lane = (half, sub): half = neighbor parity, sub = 32B
// slice of the 512B row. FULLY unrolled 16 iterations of paired 256-bit
// evict_last gathers (max front-batched MLP); fold halves with shfl_xor(16);
// lanes 0-15 stream-store the row. 128-thread CTAs for fine-grain retirement.

#define BATCH   50000
#define DEGREE  32
#define D_FEAT  128
#define WARPS_PER_BLOCK 4
#define THREADS (WARPS_PER_BLOCK * 32)
#define FULL    0xffffffffu

struct F8 { float v[8]; };

__device__ __forceinline__ F8 ldg_evict_last_v8(const float* p)
{
    F8 r;
    asm volatile(
        "ld.global.nc.L2::evict_last.v8.b32 {%0,%1,%2,%3,%4,%5,%6,%7}, [%8];"
        : "=f"(r.v[0]), "=f"(r.v[1]), "=f"(r.v[2]), "=f"(r.v[3]),
          "=f"(r.v[4]), "=f"(r.v[5]), "=f"(r.v[6]), "=f"(r.v[7])
        : "l"(p));
    return r;
}

__device__ __forceinline__ void stg_streaming_v4(float4* p, float4 v)
{
    asm volatile("st.global.cs.v4.f32 [%0], {%1,%2,%3,%4};"
                 :: "l"(p), "f"(v.x), "f"(v.y), "f"(v.z), "f"(v.w)
                 : "memory");
}

__global__ __launch_bounds__(THREADS)
void mean_agg_kernel(const void* __restrict__ neighs_raw,
                     const float* __restrict__ table,   // [500000, 128] f32
                     float4* __restrict__ out)          // [50000, 32] float4
{
    const int warp = (blockIdx.x * THREADS + threadIdx.x) >> 5;
    const int lane = threadIdx.x & 31;
    if (warp >= BATCH) return;

    const int half = lane >> 4;   // neighbor parity this lane serves
    const int sub  = lane & 15;   // 32B slice of the 512B row

    // Inline dtype detection: int64 indices in [0,500000) have zero odd 32-bit
    // words; int32 data has random indices there (P(4 zeros) ~ 1.6e-23).
    // One hot cache line for the whole grid -> broadcast hit.
    const unsigned* n32 = (const unsigned*)neighs_raw;
    const bool is64 = ((n32[1] | n32[3] | n32[5] | n32[7]) == 0u);

    // One coalesced streaming load of this node's 32 indices (lane k -> idx k).
    int my_idx;
    if (is64) {
        my_idx = (int)__ldcs(&((const long long*)neighs_raw)
                             [(size_t)warp * DEGREE + lane]);
    } else {
        my_idx = __ldcs(&((const int*)neighs_raw)
                        [(size_t)warp * DEGREE + lane]);
    }

    float acc[8] = {0.f, 0.f, 0.f, 0.f, 0.f, 0.f, 0.f, 0.f};

    // Fully unrolled: 16 independent paired gathers, maximal front-batching.
    #pragma unroll
    for (int k = 0; k < DEGREE / 2; ++k) {
        const int idx = __shfl_sync(FULL, my_idx, 2 * k + half);
        const F8 r = ldg_evict_last_v8(&table[(size_t)idx * D_FEAT + sub * 8]);
        #pragma unroll
        for (int i = 0; i < 8; ++i) acc[i] += r.v[i];
    }

    // Fold halves: lanes l and l^16 hold the same columns, disjoint k-sets.
    #pragma unroll
    for (int i = 0; i < 8; ++i)
        acc[i] += __shfl_xor_sync(FULL, acc[i], 16);

    if (half == 0) {
        const float s = 1.0f / (float)DEGREE;
        float4 lo = make_float4(acc[0] * s, acc[1] * s, acc[2] * s, acc[3] * s);
        float4 hi = make_float4(acc[4] * s, acc[5] * s, acc[6] * s, acc[7] * s);
        float4* dst = &out[(size_t)warp * (D_FEAT / 4) + sub * 2];
        stg_streaming_v4(dst, lo);
        stg_streaming_v4(dst + 1, hi);
    }
}

extern "C" void kernel_launch(void* const* d_in, const int* in_sizes, int n_in,
                              void* d_out, int out_size)
{
    const void*  neighs = d_in[0];
    const float* table  = (const float*)d_in[1];
    float4*      out    = (float4*)d_out;

    const int blocks = (BATCH + WARPS_PER_BLOCK - 1) / WARPS_PER_BLOCK;
    mean_agg_kernel<<<blocks, THREADS>>>(neighs, table, out);
}